// round 4
// baseline (speedup 1.0000x reference)
#include <cuda_runtime.h>
#include <math.h>

typedef unsigned long long u64;
typedef unsigned int u32;

// ---------------- problem constants ----------------
static const int NSUP  = 115;
static const int NQRY  = 23;
static const int NTOT  = 138;
static const int NCLS  = 23;

// ---------------- device scratch ----------------
__device__ float g_padin[(size_t)NTOT*3*258*258];    // padded input images
__device__ float g_buf0 [(size_t)NTOT*64*130*130];   // conv1 out(130) / conv3 out(34) / conv5 out(10)
__device__ float g_buf1 [(size_t)NTOT*64*66*66];     // conv2 out(66) / conv4 out(18)
__device__ u64   g_wdup [1728 + 4*36864];            // duplicated-pair weights: conv1 + conv2..5
__device__ float g_cat  [(size_t)NTOT*2048];
__device__ float g_tmp  [(size_t)NTOT*1024];
__device__ float g_h2   [(size_t)NTOT*1024];
__device__ float g_feat [(size_t)NTOT*1024];
__device__ float g_agg  [(size_t)NTOT*1024];
__device__ float g_cnt  [NTOT];
__device__ float g_b    [NQRY*NSUP];
__device__ float g_dis  [NQRY*NCLS];

// ---------------- packed f32x2 helpers ----------------
__device__ __forceinline__ u64 pk2(float x, float y){
    u64 r; asm("mov.b64 %0, {%1, %2};" : "=l"(r) : "f"(x), "f"(y)); return r;
}
__device__ __forceinline__ void fma2(u64 &d, u64 a, u64 b){
    asm("fma.rn.f32x2 %0, %1, %2, %0;" : "+l"(d) : "l"(a), "l"(b));
}
__device__ __forceinline__ float2 up2(u64 a){
    float2 r; asm("mov.b64 {%0, %1}, %2;" : "=f"(r.x), "=f"(r.y) : "l"(a)); return r;
}
// compose (a.hi, b.lo) -> ptxas lowers the 32-shifts to register moves
__device__ __forceinline__ u64 cmp2(u64 a, u64 b){ return (a >> 32) | (b << 32); }

__device__ __forceinline__ void cpa8(u32 s, const void* g){
    asm volatile("cp.async.ca.shared.global [%0], [%1], 8;" :: "r"(s), "l"(g));
}
__device__ __forceinline__ void cpa16(u32 s, const void* g){
    asm volatile("cp.async.cg.shared.global [%0], [%1], 16;" :: "r"(s), "l"(g));
}
__device__ __forceinline__ void cpa_commit(){ asm volatile("cp.async.commit_group;"); }
__device__ __forceinline__ void cpa_wait0(){ asm volatile("cp.async.wait_group 0;"); }
__device__ __forceinline__ void cpa_wait1(){ asm volatile("cp.async.wait_group 1;"); }

// ---------------- prep kernels ----------------
// pad input images: [138][3][258][258], zero border
__global__ void padin_kernel(const float* __restrict__ sx, const float* __restrict__ qx,
                             float* __restrict__ dst)
{
    size_t i = (size_t)blockIdx.x*256 + threadIdx.x;
    const size_t total = (size_t)NTOT*3*258*258;
    if (i >= total) return;
    int col = (int)(i % 258);
    size_t r1 = i / 258;
    int row = (int)(r1 % 258);
    size_t r2 = r1 / 258;
    int ch = (int)(r2 % 3);
    int img = (int)(r2 / 3);
    float v = 0.f;
    if (row >= 1 && row <= 256 && col >= 1 && col <= 256){
        const float* src = (img < NSUP)
            ? sx + ((size_t)img*3 + ch)*65536
            : qx + ((size_t)(img-NSUP)*3 + ch)*65536;
        v = src[(row-1)*256 + (col-1)];
    }
    dst[i] = v;
}

// duplicate weights into u64 pairs; conv1 at [0,1728), conv2..5 at 1728 + L*36864
// conv2..5 layout per layer: [chunk(ci/8)][oc][ci&7][tap]
__global__ void wdup_kernel(const float* __restrict__ cw1,
                            const float* __restrict__ cwr,
                            u64* __restrict__ wd)
{
    int i = blockIdx.x*256 + threadIdx.x;
    if (i < 1728){
        float v = cw1[i];
        wd[i] = pk2(v, v);
        return;
    }
    int j = i - 1728;
    if (j >= 4*36864) return;
    int L = j / 36864;
    int r = j % 36864;
    int oc = r / 576;
    int r2 = r % 576;
    int ci = r2 / 9;
    int t  = r2 % 9;
    float v = cwr[(size_t)L*36864 + (oc*64 + ci)*9 + t];
    int dst = 1728 + L*36864 + (ci >> 3)*4608 + (oc*8 + (ci & 7))*9 + t;
    wd[dst] = pk2(v, v);
}

// zero the 1-wide border of each padded channel image (P x P)
__global__ void border_kernel(float* __restrict__ buf, int P)
{
    float* b = buf + (size_t)blockIdx.x*P*P;
    for (int i = threadIdx.x; i < P; i += blockDim.x){
        b[i] = 0.f;
        b[(size_t)(P-1)*P + i] = 0.f;
        b[(size_t)i*P] = 0.f;
        b[(size_t)i*P + P-1] = 0.f;
    }
}

// ---------------- pipelined padded conv: conv3x3 + bias + relu + pool2 ----------------
// THREADS = 16*ROWS: 8 ocg x (8 px x ROWS/4 row-groups). Tile = 16 cols x ROWS rows (conv).
// Input padded [img][CIN][H+2][H+2]; output padded [img][64][PH+2][PH+2].
template<int IN_H, int ROWS, int CICH, int NCHUNK>
__global__ void __launch_bounds__(16*ROWS, 1)
convp_kernel(const float* __restrict__ in,
             const u64*  __restrict__ wdup,
             const float* __restrict__ bias,
             float* __restrict__ out)
{
    constexpr int THREADS = 16*ROWS;
    constexpr int PH   = IN_H/2;
    constexpr int H2   = IN_H + 2;
    constexpr int OP   = PH + 2;
    constexpr int TX   = PH/8;
    constexpr int TIR  = ROWS + 2;
    constexpr int PKN  = CICH*TIR*9;                  // u64 entries / chunk
    constexpr int WN   = 64*CICH*9;                   // u64 / chunk
    constexpr int NI   = (PKN + THREADS-1)/THREADS;   // 8B cp.async per thread
    constexpr int NW   = (WN/2 + THREADS-1)/THREADS;  // 16B cp.async per thread
    constexpr int CIN  = CICH*NCHUNK;
    constexpr int POS  = THREADS/8;

    extern __shared__ __align__(16) unsigned char sm[];
    u64* sIn = (u64*)sm;                              // [2][PKN]
    u64* sW  = (u64*)(sm + 2*(size_t)PKN*8);          // [2][WN]
    const u32 sInB = (u32)__cvta_generic_to_shared(sIn);
    const u32 sWB  = (u32)__cvta_generic_to_shared(sW);

    const int tid = threadIdx.x;
    const int pos = tid & (POS-1);
    const int ocg = tid / POS;
    const int px  = pos & 7;
    const int pr  = pos >> 3;
    const int img = blockIdx.y;
    const int tpy = blockIdx.x / TX, tpx = blockIdx.x % TX;
    const int cy0 = tpy*ROWS, cx0 = tpx*16;

    // ---- producer op precompute ----
    int  ginOff[NI]; u32 sinOff[NI]; bool ival[NI];
    #pragma unroll
    for (int j = 0; j < NI; j++){
        int e = tid + j*THREADS;
        ival[j] = (e < PKN);
        int ee = ival[j] ? e : 0;
        int k = ee / (TIR*9); int rem = ee - k*(TIR*9);
        int r = rem / 9;      int t = rem - r*9;
        ginOff[j] = (k*H2 + cy0 + r)*H2 + cx0 + 2*t;
        sinOff[j] = (u32)e*8;
    }

    const float* pIn = in + (size_t)img*CIN*H2*H2;
    const u64*   pW  = wdup;

    // ---- prologue ----
    #pragma unroll
    for (int j = 0; j < NI; j++)
        if (ival[j]) cpa8(sInB + sinOff[j], pIn + ginOff[j]);
    #pragma unroll
    for (int j = 0; j < NW; j++){
        int e2 = tid + j*THREADS;
        if (e2 < WN/2) cpa16(sWB + (u32)e2*16, (const char*)pW + (size_t)e2*16);
    }
    cpa_commit();
    if (NCHUNK > 1){
        pIn += CICH*H2*H2; pW += WN;
        #pragma unroll
        for (int j = 0; j < NI; j++)
            if (ival[j]) cpa8(sInB + (u32)PKN*8 + sinOff[j], pIn + ginOff[j]);
        #pragma unroll
        for (int j = 0; j < NW; j++){
            int e2 = tid + j*THREADS;
            if (e2 < WN/2) cpa16(sWB + (u32)WN*8 + (u32)e2*16, (const char*)pW + (size_t)e2*16);
        }
        cpa_commit();
    }

    u64 acc[8][4];
    #pragma unroll
    for (int o = 0; o < 8; o++)
        #pragma unroll
        for (int cc = 0; cc < 4; cc++) acc[o][cc] = 0ull;

    // ---- main loop ----
    #pragma unroll 1
    for (int c = 0; c < NCHUNK; c++){
        if (NCHUNK > 1) cpa_wait1(); else cpa_wait0();
        __syncthreads();

        const int buf = c & 1;
        const u64* pkb = sIn + buf*PKN;
        const u64* wbb = sW  + buf*WN;

        #pragma unroll
        for (int kk = 0; kk < CICH; kk++){
            const u64* prow = pkb + (kk*TIR + 4*pr)*9;
            u64 B0[6], B1[6], P1[6];
            #pragma unroll
            for (int r = 0; r < 6; r++){
                B0[r] = prow[r*9 + px];
                B1[r] = prow[r*9 + px + 1];
                P1[r] = cmp2(B0[r], B1[r]);
            }
            #pragma unroll
            for (int o = 0; o < 8; o++){
                const u64* wp = wbb + ((ocg*8 + o)*CICH + kk)*9;
                #pragma unroll
                for (int dy = 0; dy < 3; dy++){
                    u64 w0 = wp[dy*3+0], w1 = wp[dy*3+1], w2 = wp[dy*3+2];
                    #pragma unroll
                    for (int cc = 0; cc < 4; cc++) fma2(acc[o][cc], B0[cc+dy], w0);
                    #pragma unroll
                    for (int cc = 0; cc < 4; cc++) fma2(acc[o][cc], P1[cc+dy], w1);
                    #pragma unroll
                    for (int cc = 0; cc < 4; cc++) fma2(acc[o][cc], B1[cc+dy], w2);
                }
            }
        }

        if (c + 1 == NCHUNK) break;
        __syncthreads();

        if (c + 2 < NCHUNK){
            pIn += CICH*H2*H2; pW += WN;
            #pragma unroll
            for (int j = 0; j < NI; j++)
                if (ival[j]) cpa8(sInB + (u32)buf*PKN*8 + sinOff[j], pIn + ginOff[j]);
            #pragma unroll
            for (int j = 0; j < NW; j++){
                int e2 = tid + j*THREADS;
                if (e2 < WN/2) cpa16(sWB + (u32)buf*WN*8 + (u32)e2*16, (const char*)pW + (size_t)e2*16);
            }
        }
        cpa_commit();
    }

    // ---- epilogue: pool 2x2, bias, relu; store into padded output interior ----
    const int gx  = tpx*8 + px;
    const int gy0 = tpy*(ROWS/2) + 2*pr;
    #pragma unroll
    for (int o = 0; o < 8; o++){
        int oc = ocg*8 + o;
        float b = bias[oc];
        float2 a0 = up2(acc[o][0]), a1 = up2(acc[o][1]);
        float2 a2 = up2(acc[o][2]), a3 = up2(acc[o][3]);
        float m0 = fmaxf(fmaxf(a0.x,a0.y), fmaxf(a1.x,a1.y)) + b; m0 = fmaxf(m0, 0.f);
        float m1 = fmaxf(fmaxf(a2.x,a2.y), fmaxf(a3.x,a3.y)) + b; m1 = fmaxf(m1, 0.f);
        float* op = out + ((size_t)img*64 + oc)*OP*OP;
        op[(size_t)(gy0+1)*OP + gx+1] = m0;
        op[(size_t)(gy0+2)*OP + gx+1] = m1;
    }
}

// ---------------- conv6: 64->64 on 8x8 (padded 10x10 input), flatten to g_cat ----------------
__global__ void conv6_kernel(const float* __restrict__ in,   // padded [img][64][10][10]
                             const float* __restrict__ w,
                             const float* __restrict__ bias,
                             float* __restrict__ out)         // g_cat stride 2048
{
    constexpr int TI = 10, CHUNK = 8;
    __shared__ __align__(16) float sIn[CHUNK][TI][TI];
    __shared__ u64 sW[64][CHUNK][9];

    const int tid = threadIdx.x;          // 128
    const int pos = tid & 15;             // 4x4 pooled positions
    const int ocg = tid >> 4;             // 8 groups x 8 oc
    const int py = pos >> 2, px = pos & 3;
    const int img = blockIdx.x;
    const float* inImg = in + (size_t)img*64*100;

    u64 accA[8], accB[8];
    #pragma unroll
    for (int i = 0; i < 8; i++){ accA[i]=0ull; accB[i]=0ull; }

    for (int ci0 = 0; ci0 < 64; ci0 += CHUNK){
        for (int idx = tid; idx < CHUNK*TI*TI; idx += 128){
            int k = idx/100, rem = idx%100;
            sIn[k][rem/10][rem%10] = inImg[(size_t)(ci0+k)*100 + rem];
        }
        for (int idx = tid; idx < 64*CHUNK*9; idx += 128){
            int oc = idx/(CHUNK*9), rem = idx%(CHUNK*9);
            int k = rem/9, t = rem%9;
            float wv = w[(oc*64 + (ci0+k))*9 + t];
            sW[oc][k][t] = pk2(wv, wv);
        }
        __syncthreads();

        #pragma unroll
        for (int k = 0; k < CHUNK; k++){
            u64 P[4][3];
            #pragma unroll
            for (int r = 0; r < 4; r++){
                float2 a = *(const float2*)&sIn[k][2*py+r][2*px];
                float2 b = *(const float2*)&sIn[k][2*py+r][2*px+2];
                P[r][0] = pk2(a.x, a.y);
                P[r][1] = pk2(a.y, b.x);
                P[r][2] = pk2(b.x, b.y);
            }
            #pragma unroll
            for (int o = 0; o < 8; o++){
                const u64* wp = &sW[ocg*8+o][k][0];
                #pragma unroll
                for (int dy = 0; dy < 3; dy++){
                    #pragma unroll
                    for (int dx = 0; dx < 3; dx++){
                        u64 wv = wp[dy*3+dx];
                        fma2(accA[o], P[dy][dx],   wv);
                        fma2(accB[o], P[dy+1][dx], wv);
                    }
                }
            }
        }
        __syncthreads();
    }

    #pragma unroll
    for (int o = 0; o < 8; o++){
        int oc = ocg*8 + o;
        float2 ca = up2(accA[o]); float2 cb = up2(accB[o]);
        float m = fmaxf(fmaxf(ca.x,ca.y), fmaxf(cb.x,cb.y)) + bias[oc];
        m = fmaxf(m, 0.f);
        // flatten order: oc*16 + y*4 + x  (matches h1 layout)
        out[(size_t)img*2048 + oc*16 + py*4 + px] = m;
    }
}

// ---------------- small kernels ----------------
__global__ void zero_kernel(float* __restrict__ p, int n){
    int i = blockIdx.x*256 + threadIdx.x;
    if (i < n) p[i] = 0.f;
}

__global__ void scatter_kernel(const float* __restrict__ feat, int stride, int colOff,
                               const int* __restrict__ ei, int E, int base,
                               float* __restrict__ agg, float* __restrict__ cnt)
{
    int e = blockIdx.x;
    int src = ei[e], dst = ei[E + e];
    const float* f = feat + (size_t)(base+src)*stride + colOff;
    float* a = agg + (size_t)(base+dst)*1024;
    for (int d = threadIdx.x; d < 1024; d += blockDim.x)
        atomicAdd(&a[d], f[d]);
    if (threadIdx.x == 0) atomicAdd(&cnt[base+dst], 1.f);
}

__global__ void combine_kernel(const float* __restrict__ feat, int fstride, int fcolOff,
                               const float* __restrict__ agg, const float* __restrict__ cnt,
                               float* __restrict__ outp, int ostride, int ocolOff)
{
    int i = blockIdx.x*256 + threadIdx.x;
    if (i >= NTOT*1024) return;
    int n = i >> 10, d = i & 1023;
    float c = fmaxf(cnt[n], 1.f);
    float fv = feat[(size_t)n*fstride + fcolOff + d];
    outp[(size_t)n*ostride + ocolOff + d] = (agg[i]/c) * fv;
}

__global__ void gemm_bias_kernel(const float* __restrict__ A, int lda,
                                 const float* __restrict__ W,
                                 const float* __restrict__ bias,
                                 float* __restrict__ C, int M, int K)
{
    __shared__ float sA[16][17];
    __shared__ float sB[16][64];
    int tx = threadIdx.x & 15, ty = threadIdx.x >> 4;
    int n0 = blockIdx.x*64, m0 = blockIdx.y*16;
    float acc[4] = {0.f,0.f,0.f,0.f};
    for (int k0 = 0; k0 < K; k0 += 16){
        int m = m0 + ty;
        sA[ty][tx] = (m < M) ? A[(size_t)m*lda + k0 + tx] : 0.f;
        #pragma unroll
        for (int j = 0; j < 4; j++)
            sB[ty][tx*4+j] = W[(size_t)(k0+ty)*1024 + n0 + tx*4 + j];
        __syncthreads();
        #pragma unroll
        for (int kk = 0; kk < 16; kk++){
            float a = sA[ty][kk];
            #pragma unroll
            for (int j = 0; j < 4; j++) acc[j] += a * sB[kk][tx*4+j];
        }
        __syncthreads();
    }
    int m = m0 + ty;
    if (m < M){
        #pragma unroll
        for (int j = 0; j < 4; j++)
            C[(size_t)m*1024 + n0 + tx*4 + j] = acc[j] + bias[n0 + tx*4 + j];
    }
}

__global__ void pair_kernel(const float* __restrict__ feat,
                            const float* __restrict__ center,
                            float* __restrict__ bmat)
{
    int s = blockIdx.x, q = blockIdx.y;
    const float* qf = feat + (size_t)(NSUP+q)*1024;
    const float* sf = feat + (size_t)s*1024;
    const float* cf = center + (size_t)(s/5)*1024;
    __shared__ float su[1024];
    __shared__ float rA[256], rB[256], rC[256];
    __shared__ float sS1, sS2;
    int tid = threadIdx.x;

    float S1 = 0.f, S2 = 0.f, M = -1e30f;
    for (int d = tid; d < 1024; d += 256){
        float qd = qf[d], sd = sf[d];
        float df = sd - qd;
        float u = expf(-df*df);
        su[d] = u;
        S2 += u; M = fmaxf(M, u);
        float sc = 0.25f*cf[d] + 0.5f*sd;
        float d2 = sc - qd;
        S1 += expf(-d2*d2);
    }
    rA[tid]=S1; rB[tid]=S2; rC[tid]=M;
    __syncthreads();
    for (int o = 128; o > 0; o >>= 1){
        if (tid < o){ rA[tid]+=rA[tid+o]; rB[tid]+=rB[tid+o]; rC[tid]=fmaxf(rC[tid],rC[tid+o]); }
        __syncthreads();
    }
    if (tid == 0){ sS1 = rA[0]; sS2 = rB[0]; }
    float Mv = rC[0];
    __syncthreads();

    float Se = 0.f;
    for (int d = tid; d < 1024; d += 256) Se += expf(su[d] - Mv);
    rA[tid] = Se;
    __syncthreads();
    for (int o = 128; o > 0; o >>= 1){ if (tid < o) rA[tid]+=rA[tid+o]; __syncthreads(); }
    if (tid == 0)
        bmat[q*NSUP + s] = sS1 + sS2 - 1024.f*(Mv + logf(rA[0]));
}

__global__ void dis_kernel(const float* __restrict__ bmat,
                           const int* __restrict__ sy,
                           float* __restrict__ dis)
{
    int q = blockIdx.x;
    __shared__ float row[NSUP];
    __shared__ float red[128];
    int tid = threadIdx.x;
    float m = -1e30f;
    for (int s = tid; s < NSUP; s += 128){ row[s] = bmat[q*NSUP+s]; m = fmaxf(m, row[s]); }
    red[tid] = m; __syncthreads();
    for (int o = 64; o > 0; o >>= 1){ if (tid < o) red[tid]=fmaxf(red[tid],red[tid+o]); __syncthreads(); }
    float mv = red[0]; __syncthreads();
    float se = 0.f;
    for (int s = tid; s < NSUP; s += 128) se += expf(row[s]-mv);
    red[tid] = se; __syncthreads();
    for (int o = 64; o > 0; o >>= 1){ if (tid < o) red[tid]+=red[tid+o]; __syncthreads(); }
    float lse = mv + logf(red[0]);
    if (tid < NCLS){
        float sum = 0.f, cntc = 0.f;
        for (int s = 0; s < NSUP; s++) if (sy[s]==tid){ sum += row[s]-lse; cntc += 1.f; }
        dis[q*NCLS+tid] = sum / fmaxf(cntc, 1.f);
    }
}

__global__ void center_kernel(const float* __restrict__ feat,
                              const int* __restrict__ sy,
                              const float* __restrict__ center,
                              float* __restrict__ outp)
{
    int c = blockIdx.x;
    int d = blockIdx.y*256 + threadIdx.x;
    __shared__ int ssy[NSUP];
    for (int s = threadIdx.x; s < NSUP; s += 256) ssy[s] = sy[s];
    __syncthreads();
    float sum = 0.f, cnt = 0.f;
    for (int s = 0; s < NSUP; s++) if (ssy[s]==c){ sum += feat[(size_t)s*1024 + d]; cnt += 1.f; }
    outp[c*1024 + d] = (sum/fmaxf(cnt,1.f))*0.5f + 0.25f*center[c*1024 + d];
}

__global__ void loss_kernel(const float* __restrict__ dis,
                            const int* __restrict__ qy,
                            float* __restrict__ outp)
{
    __shared__ float sl[32], sa[32];
    int q = threadIdx.x;
    float l = 0.f, a = 0.f;
    if (q < NQRY){
        const float* r = dis + q*NCLS;
        float best = -1e30f; int arg = 0; float m = -1e30f;
        for (int j = 0; j < NCLS; j++){
            float v = r[j];
            if (v > best){ best = v; arg = j; }
            m = fmaxf(m, v);
        }
        float se = 0.f;
        for (int j = 0; j < NCLS; j++) se += expf(r[j]-m);
        float lse = m + logf(se);
        int y = qy[q];
        l = lse - r[y];
        a = (arg == y) ? 1.f : 0.f;
    }
    sl[threadIdx.x] = l; sa[threadIdx.x] = a;
    __syncthreads();
    if (threadIdx.x == 0){
        float L = 0.f, A = 0.f;
        for (int i = 0; i < 32; i++){ L += sl[i]; A += sa[i]; }
        outp[0] = L; outp[1] = A;
    }
}

// ---------------- host launcher ----------------
extern "C" void kernel_launch(void* const* d_in, const int* in_sizes, int n_in,
                              void* d_out, int out_size)
{
    const float* support_x = (const float*)d_in[0];
    const int*   sup_ei    = (const int*)  d_in[1];
    const int*   sup_y     = (const int*)  d_in[3];
    const float* query_x   = (const float*)d_in[4];
    const int*   qry_ei    = (const int*)  d_in[5];
    const int*   qry_y     = (const int*)  d_in[7];
    const float* center    = (const float*)d_in[8];
    const float* cw1       = (const float*)d_in[9];
    const float* cb1       = (const float*)d_in[10];
    const float* cw_rest   = (const float*)d_in[11];
    const float* cb_rest   = (const float*)d_in[12];
    const float* lin2_w    = (const float*)d_in[13];
    const float* lin2_b    = (const float*)d_in[14];
    const float* mlp_w     = (const float*)d_in[15];
    const float* mlp_b     = (const float*)d_in[16];
    float* out = (float*)d_out;

    int Es = in_sizes[1] / 2;
    int Eq = in_sizes[5] / 2;

    float *padin, *buf0, *buf1, *cat, *tmp, *h2, *feat, *agg, *cnt, *bmat, *dis;
    u64* wdup;
    cudaGetSymbolAddress((void**)&padin, g_padin);
    cudaGetSymbolAddress((void**)&buf0,  g_buf0);
    cudaGetSymbolAddress((void**)&buf1,  g_buf1);
    cudaGetSymbolAddress((void**)&wdup,  g_wdup);
    cudaGetSymbolAddress((void**)&cat,   g_cat);
    cudaGetSymbolAddress((void**)&tmp,   g_tmp);
    cudaGetSymbolAddress((void**)&h2,    g_h2);
    cudaGetSymbolAddress((void**)&feat,  g_feat);
    cudaGetSymbolAddress((void**)&agg,   g_agg);
    cudaGetSymbolAddress((void**)&cnt,   g_cnt);
    cudaGetSymbolAddress((void**)&bmat,  g_b);
    cudaGetSymbolAddress((void**)&dis,   g_dis);

    // dynamic smem sizes per instantiation
    const int SM_C1 = 2*(3*34*9)*8  + 2*(64*3*9)*8;   // 42336
    const int SM_C2 = 2*(8*34*9)*8  + 2*(64*8*9)*8;   // 112896
    const int SM_C5 = 2*(8*18*9)*8  + 2*(64*8*9)*8;   // 94464

    static int attr_done = 0;
    if (!attr_done){
        cudaFuncSetAttribute(convp_kernel<256,32,3,1>, cudaFuncAttributeMaxDynamicSharedMemorySize, SM_C1);
        cudaFuncSetAttribute(convp_kernel<128,32,8,8>, cudaFuncAttributeMaxDynamicSharedMemorySize, SM_C2);
        cudaFuncSetAttribute(convp_kernel< 64,32,8,8>, cudaFuncAttributeMaxDynamicSharedMemorySize, SM_C2);
        cudaFuncSetAttribute(convp_kernel< 32,32,8,8>, cudaFuncAttributeMaxDynamicSharedMemorySize, SM_C2);
        cudaFuncSetAttribute(convp_kernel< 16,16,8,8>, cudaFuncAttributeMaxDynamicSharedMemorySize, SM_C5);
        attr_done = 1;
    }

    // ---- prep ----
    {
        size_t total = (size_t)NTOT*3*258*258;
        padin_kernel<<<(unsigned)((total + 255)/256), 256>>>(support_x, query_x, padin);
    }
    wdup_kernel<<<(1728 + 4*36864 + 255)/256, 256>>>(cw1, cw_rest, wdup);
    border_kernel<<<NTOT*64, 64>>>(buf0, 130);
    border_kernel<<<NTOT*64, 64>>>(buf1, 66);

    // ---- CNN ----
    // conv1: 3->64, 256 -> pooled 128 (padded out 130)
    convp_kernel<256,32,3,1><<<dim3(16*8, NTOT), 512, SM_C1>>>(padin, wdup, cb1, buf0);
    // conv2: 128 -> 64 (out 66)
    convp_kernel<128,32,8,8><<<dim3(8*4, NTOT), 512, SM_C2>>>(buf0, wdup + 1728 + 0*36864, cb_rest + 0,   buf1);
    border_kernel<<<NTOT*64, 64>>>(buf0, 34);
    // conv3: 64 -> 32 (out 34)
    convp_kernel< 64,32,8,8><<<dim3(4*2, NTOT), 512, SM_C2>>>(buf1, wdup + 1728 + 1*36864, cb_rest + 64,  buf0);
    border_kernel<<<NTOT*64, 64>>>(buf1, 18);
    // conv4: 32 -> 16 (out 18)
    convp_kernel< 32,32,8,8><<<dim3(2*1, NTOT), 512, SM_C2>>>(buf0, wdup + 1728 + 2*36864, cb_rest + 128, buf1);
    border_kernel<<<NTOT*64, 64>>>(buf0, 10);
    // conv5: 16 -> 8 (out 10)
    convp_kernel< 16,16,8,8><<<dim3(1, NTOT), 256, SM_C5>>>(buf1, wdup + 1728 + 3*36864, cb_rest + 192, buf0);
    // conv6: 8 -> 4, flatten into g_cat[:,0:1024]
    conv6_kernel<<<NTOT, 128>>>(buf0, cw_rest + 4*(64*64*9), cb_rest + 256, cat);

    const int NG = (NTOT*1024 + 255)/256;

    // ---- graph conv 1 ----
    zero_kernel<<<NG,256>>>(agg, NTOT*1024);
    zero_kernel<<<1,256>>>(cnt, NTOT);
    scatter_kernel<<<Es,256>>>(cat, 2048, 0, sup_ei, Es, 0,    agg, cnt);
    scatter_kernel<<<Eq,256>>>(cat, 2048, 0, qry_ei, Eq, NSUP, agg, cnt);
    combine_kernel<<<NG,256>>>(cat, 2048, 0, agg, cnt, tmp, 1024, 0);

    gemm_bias_kernel<<<dim3(16,(NTOT+15)/16),256>>>(tmp, 1024, lin2_w, lin2_b, h2, NTOT, 1024);

    // ---- graph conv 2 ----
    zero_kernel<<<NG,256>>>(agg, NTOT*1024);
    zero_kernel<<<1,256>>>(cnt, NTOT);
    scatter_kernel<<<Es,256>>>(h2, 1024, 0, sup_ei, Es, 0,    agg, cnt);
    scatter_kernel<<<Eq,256>>>(h2, 1024, 0, qry_ei, Eq, NSUP, agg, cnt);
    combine_kernel<<<NG,256>>>(h2, 1024, 0, agg, cnt, cat, 2048, 1024);

    gemm_bias_kernel<<<dim3(16,(NTOT+15)/16),256>>>(cat, 2048, mlp_w, mlp_b, feat, NTOT, 2048);

    pair_kernel<<<dim3(NSUP, NQRY), 256>>>(feat, center, bmat);
    dis_kernel<<<NQRY,128>>>(bmat, sup_y, dis);

    center_kernel<<<dim3(NCLS,4),256>>>(feat, sup_y, center, out + 2);
    loss_kernel<<<1,32>>>(dis, qry_y, out);
}

// round 5
// speedup vs baseline: 1.0256x; 1.0256x over previous
#include <cuda_runtime.h>
#include <math.h>

typedef unsigned long long u64;
typedef unsigned int u32;

// ---------------- problem constants ----------------
static const int NSUP  = 115;
static const int NQRY  = 23;
static const int NTOT  = 138;
static const int NCLS  = 23;

// ---------------- device scratch ----------------
__device__ float g_padin[(size_t)NTOT*3*258*258];    // padded input images
__device__ float g_buf0 [(size_t)NTOT*64*130*130];   // conv1 out(130) / conv3 out(34) / conv5 out(10)
__device__ float g_buf1 [(size_t)NTOT*64*66*66];     // conv2 out(66) / conv4 out(18)
__device__ u64   g_wdup [1728 + 4*36864];            // duplicated-pair weights
__device__ float g_cat  [(size_t)NTOT*2048];
__device__ float g_tmp  [(size_t)NTOT*1024];
__device__ float g_h2   [(size_t)NTOT*1024];
__device__ float g_feat [(size_t)NTOT*1024];
__device__ float g_agg  [(size_t)NTOT*1024];
__device__ float g_cnt  [NTOT];
__device__ float g_b    [NQRY*NSUP];
__device__ float g_dis  [NQRY*NCLS];

// ---------------- packed f32x2 helpers ----------------
__device__ __forceinline__ u64 pk2(float x, float y){
    u64 r; asm("mov.b64 %0, {%1, %2};" : "=l"(r) : "f"(x), "f"(y)); return r;
}
__device__ __forceinline__ void fma2(u64 &d, u64 a, u64 b){
    asm("fma.rn.f32x2 %0, %1, %2, %0;" : "+l"(d) : "l"(a), "l"(b));
}
__device__ __forceinline__ float2 up2(u64 a){
    float2 r; asm("mov.b64 {%0, %1}, %2;" : "=f"(r.x), "=f"(r.y) : "l"(a)); return r;
}
__device__ __forceinline__ u64 cmp2(u64 a, u64 b){ return (a >> 32) | (b << 32); }

__device__ __forceinline__ void cpa8(u32 s, const void* g){
    asm volatile("cp.async.ca.shared.global [%0], [%1], 8;" :: "r"(s), "l"(g));
}
__device__ __forceinline__ void cpa16(u32 s, const void* g){
    asm volatile("cp.async.cg.shared.global [%0], [%1], 16;" :: "r"(s), "l"(g));
}
__device__ __forceinline__ void cpa_commit(){ asm volatile("cp.async.commit_group;"); }
__device__ __forceinline__ void cpa_wait0(){ asm volatile("cp.async.wait_group 0;"); }
__device__ __forceinline__ void cpa_wait1(){ asm volatile("cp.async.wait_group 1;"); }

// ---------------- prep kernels ----------------
__global__ void padin_kernel(const float* __restrict__ sx, const float* __restrict__ qx,
                             float* __restrict__ dst)
{
    size_t i = (size_t)blockIdx.x*256 + threadIdx.x;
    const size_t total = (size_t)NTOT*3*258*258;
    if (i >= total) return;
    int col = (int)(i % 258);
    size_t r1 = i / 258;
    int row = (int)(r1 % 258);
    size_t r2 = r1 / 258;
    int ch = (int)(r2 % 3);
    int img = (int)(r2 / 3);
    float v = 0.f;
    if (row >= 1 && row <= 256 && col >= 1 && col <= 256){
        const float* src = (img < NSUP)
            ? sx + ((size_t)img*3 + ch)*65536
            : qx + ((size_t)(img-NSUP)*3 + ch)*65536;
        v = src[(row-1)*256 + (col-1)];
    }
    dst[i] = v;
}

// conv1 at [0,1728) verbatim-dup; conv2..5 at 1728 + L*36864, layout [chunk][oc][ci&7][tap]
__global__ void wdup_kernel(const float* __restrict__ cw1,
                            const float* __restrict__ cwr,
                            u64* __restrict__ wd)
{
    int i = blockIdx.x*256 + threadIdx.x;
    if (i < 1728){
        float v = cw1[i];
        wd[i] = pk2(v, v);
        return;
    }
    int j = i - 1728;
    if (j >= 4*36864) return;
    int L = j / 36864;
    int r = j % 36864;
    int oc = r / 576;
    int r2 = r % 576;
    int ci = r2 / 9;
    int t  = r2 % 9;
    float v = cwr[(size_t)L*36864 + (oc*64 + ci)*9 + t];
    int dst = 1728 + L*36864 + (ci >> 3)*4608 + (oc*8 + (ci & 7))*9 + t;
    wd[dst] = pk2(v, v);
}

__global__ void border_kernel(float* __restrict__ buf, int P)
{
    float* b = buf + (size_t)blockIdx.x*P*P;
    for (int i = threadIdx.x; i < P; i += blockDim.x){
        b[i] = 0.f;
        b[(size_t)(P-1)*P + i] = 0.f;
        b[(size_t)i*P] = 0.f;
        b[(size_t)i*P + P-1] = 0.f;
    }
}

// ---------------- pipelined padded conv: conv3x3 + bias + relu + pool2 ----------------
// 512 thr = 16 ocg (4 oc each) x 32 pos (px=pos>>2 in 0..7 col-pairs, pr=pos&3 row-groups)
// Tile = 16 conv cols x 16 conv rows. Input/output padded with zero border.
template<int IN_H, int CICH, int NCHUNK>
__global__ void __launch_bounds__(512, 1)
convp_kernel(const float* __restrict__ in,
             const u64*  __restrict__ wdup,
             const float* __restrict__ bias,
             float* __restrict__ out)
{
    constexpr int THREADS = 512;
    constexpr int PH  = IN_H/2;
    constexpr int H2  = IN_H + 2;
    constexpr int OP  = PH + 2;
    constexpr int TX  = PH/8;
    constexpr int TIR = 18;
    constexpr int PKN = CICH*TIR*9;
    constexpr int WN  = 64*CICH*9;
    constexpr int NI  = (PKN + THREADS-1)/THREADS;
    constexpr int NW  = (WN/2 + THREADS-1)/THREADS;
    constexpr int CIN = CICH*NCHUNK;

    extern __shared__ __align__(16) unsigned char sm[];
    u64* sIn = (u64*)sm;                          // [2][PKN]
    u64* sW  = (u64*)(sm + 2*(size_t)PKN*8);      // [2][WN]
    const u32 sInB = (u32)__cvta_generic_to_shared(sIn);
    const u32 sWB  = (u32)__cvta_generic_to_shared(sW);

    const int tid = threadIdx.x;
    const int pos = tid & 31;
    const int ocg = tid >> 5;          // 0..15
    const int pr  = pos & 3;           // row-group
    const int px  = pos >> 2;          // 0..7 col-pair
    const int img = blockIdx.y;
    const int tpy = blockIdx.x / TX, tpx = blockIdx.x % TX;
    const int cy0 = tpy*16, cx0 = tpx*16;

    // producer precompute
    int ginOff[NI]; u32 sinOff[NI]; bool ival[NI];
    #pragma unroll
    for (int j = 0; j < NI; j++){
        int e = tid + j*THREADS;
        ival[j] = (e < PKN);
        int ee = ival[j] ? e : 0;
        int k = ee / (TIR*9); int rem = ee - k*(TIR*9);
        int r = rem / 9;      int t = rem - r*9;
        ginOff[j] = (k*H2 + cy0 + r)*H2 + cx0 + 2*t;
        sinOff[j] = (u32)e*8;
    }

    const float* pIn = in + (size_t)img*CIN*H2*H2;
    const u64*   pW  = wdup;

    // prologue
    #pragma unroll
    for (int j = 0; j < NI; j++)
        if (ival[j]) cpa8(sInB + sinOff[j], pIn + ginOff[j]);
    #pragma unroll
    for (int j = 0; j < NW; j++){
        int e2 = tid + j*THREADS;
        if (e2 < WN/2) cpa16(sWB + (u32)e2*16, (const char*)pW + (size_t)e2*16);
    }
    cpa_commit();
    if (NCHUNK > 1){
        pIn += CICH*H2*H2; pW += WN;
        #pragma unroll
        for (int j = 0; j < NI; j++)
            if (ival[j]) cpa8(sInB + (u32)PKN*8 + sinOff[j], pIn + ginOff[j]);
        #pragma unroll
        for (int j = 0; j < NW; j++){
            int e2 = tid + j*THREADS;
            if (e2 < WN/2) cpa16(sWB + (u32)WN*8 + (u32)e2*16, (const char*)pW + (size_t)e2*16);
        }
        cpa_commit();
    }

    u64 acc[4][4];
    #pragma unroll
    for (int o = 0; o < 4; o++)
        #pragma unroll
        for (int cc = 0; cc < 4; cc++) acc[o][cc] = 0ull;

    // main loop
    #pragma unroll 1
    for (int c = 0; c < NCHUNK; c++){
        if (NCHUNK > 1) cpa_wait1(); else cpa_wait0();
        __syncthreads();

        const int buf = c & 1;
        const u64* pkb = sIn + buf*PKN;
        const u64* wbb = sW  + buf*WN;

        #pragma unroll
        for (int kk = 0; kk < CICH; kk++){
            const u64* prow = pkb + (kk*TIR + 4*pr)*9;
            u64 B0[6], B1[6], P1[6];
            #pragma unroll
            for (int r = 0; r < 6; r++){
                B0[r] = prow[r*9 + px];
                B1[r] = prow[r*9 + px + 1];
                P1[r] = cmp2(B0[r], B1[r]);
            }
            #pragma unroll
            for (int o = 0; o < 4; o++){
                const u64* wp = wbb + ((ocg*4 + o)*CICH + kk)*9;
                #pragma unroll
                for (int dy = 0; dy < 3; dy++){
                    u64 w0 = wp[dy*3+0], w1 = wp[dy*3+1], w2 = wp[dy*3+2];
                    #pragma unroll
                    for (int cc = 0; cc < 4; cc++) fma2(acc[o][cc], B0[cc+dy], w0);
                    #pragma unroll
                    for (int cc = 0; cc < 4; cc++) fma2(acc[o][cc], P1[cc+dy], w1);
                    #pragma unroll
                    for (int cc = 0; cc < 4; cc++) fma2(acc[o][cc], B1[cc+dy], w2);
                }
            }
        }

        if (c + 1 == NCHUNK) break;
        __syncthreads();

        if (c + 2 < NCHUNK){
            pIn += CICH*H2*H2; pW += WN;
            #pragma unroll
            for (int j = 0; j < NI; j++)
                if (ival[j]) cpa8(sInB + (u32)buf*PKN*8 + sinOff[j], pIn + ginOff[j]);
            #pragma unroll
            for (int j = 0; j < NW; j++){
                int e2 = tid + j*THREADS;
                if (e2 < WN/2) cpa16(sWB + (u32)buf*WN*8 + (u32)e2*16, (const char*)pW + (size_t)e2*16);
            }
        }
        cpa_commit();
    }

    // epilogue: pool 2x2, bias, relu; store padded interior
    const int gx  = tpx*8 + px;
    const int gy0 = tpy*8 + 2*pr;
    #pragma unroll
    for (int o = 0; o < 4; o++){
        int oc = ocg*4 + o;
        float b = bias[oc];
        float2 a0 = up2(acc[o][0]), a1 = up2(acc[o][1]);
        float2 a2 = up2(acc[o][2]), a3 = up2(acc[o][3]);
        float m0 = fmaxf(fmaxf(a0.x,a0.y), fmaxf(a1.x,a1.y)) + b; m0 = fmaxf(m0, 0.f);
        float m1 = fmaxf(fmaxf(a2.x,a2.y), fmaxf(a3.x,a3.y)) + b; m1 = fmaxf(m1, 0.f);
        float* op = out + ((size_t)img*64 + oc)*OP*OP;
        op[(size_t)(gy0+1)*OP + gx+1] = m0;
        op[(size_t)(gy0+2)*OP + gx+1] = m1;
    }
}

// ---------------- conv6: 64->64 on 8x8 (padded 10x10 input), flatten to g_cat ----------------
__global__ void conv6_kernel(const float* __restrict__ in,
                             const float* __restrict__ w,
                             const float* __restrict__ bias,
                             float* __restrict__ out)
{
    constexpr int TI = 10, CHUNK = 8;
    __shared__ __align__(16) float sIn[CHUNK][TI][TI];
    __shared__ u64 sW[64][CHUNK][9];

    const int tid = threadIdx.x;          // 128
    const int pos = tid & 15;
    const int ocg = tid >> 4;
    const int py = pos >> 2, px = pos & 3;
    const int img = blockIdx.x;
    const float* inImg = in + (size_t)img*64*100;

    u64 accA[8], accB[8];
    #pragma unroll
    for (int i = 0; i < 8; i++){ accA[i]=0ull; accB[i]=0ull; }

    for (int ci0 = 0; ci0 < 64; ci0 += CHUNK){
        for (int idx = tid; idx < CHUNK*TI*TI; idx += 128){
            int k = idx/100, rem = idx%100;
            sIn[k][rem/10][rem%10] = inImg[(size_t)(ci0+k)*100 + rem];
        }
        for (int idx = tid; idx < 64*CHUNK*9; idx += 128){
            int oc = idx/(CHUNK*9), rem = idx%(CHUNK*9);
            int k = rem/9, t = rem%9;
            float wv = w[(oc*64 + (ci0+k))*9 + t];
            sW[oc][k][t] = pk2(wv, wv);
        }
        __syncthreads();

        #pragma unroll
        for (int k = 0; k < CHUNK; k++){
            u64 P[4][3];
            #pragma unroll
            for (int r = 0; r < 4; r++){
                float2 a = *(const float2*)&sIn[k][2*py+r][2*px];
                float2 b = *(const float2*)&sIn[k][2*py+r][2*px+2];
                P[r][0] = pk2(a.x, a.y);
                P[r][1] = pk2(a.y, b.x);
                P[r][2] = pk2(b.x, b.y);
            }
            #pragma unroll
            for (int o = 0; o < 8; o++){
                const u64* wp = &sW[ocg*8+o][k][0];
                #pragma unroll
                for (int dy = 0; dy < 3; dy++){
                    #pragma unroll
                    for (int dx = 0; dx < 3; dx++){
                        u64 wv = wp[dy*3+dx];
                        fma2(accA[o], P[dy][dx],   wv);
                        fma2(accB[o], P[dy+1][dx], wv);
                    }
                }
            }
        }
        __syncthreads();
    }

    #pragma unroll
    for (int o = 0; o < 8; o++){
        int oc = ocg*8 + o;
        float2 ca = up2(accA[o]); float2 cb = up2(accB[o]);
        float m = fmaxf(fmaxf(ca.x,ca.y), fmaxf(cb.x,cb.y)) + bias[oc];
        m = fmaxf(m, 0.f);
        out[(size_t)img*2048 + oc*16 + py*4 + px] = m;
    }
}

// ---------------- small kernels ----------------
__global__ void zero_kernel(float* __restrict__ p, int n){
    int i = blockIdx.x*256 + threadIdx.x;
    if (i < n) p[i] = 0.f;
}

__global__ void scatter_kernel(const float* __restrict__ feat, int stride, int colOff,
                               const int* __restrict__ ei, int E, int base,
                               float* __restrict__ agg, float* __restrict__ cnt)
{
    int e = blockIdx.x;
    int src = ei[e], dst = ei[E + e];
    const float* f = feat + (size_t)(base+src)*stride + colOff;
    float* a = agg + (size_t)(base+dst)*1024;
    for (int d = threadIdx.x; d < 1024; d += blockDim.x)
        atomicAdd(&a[d], f[d]);
    if (threadIdx.x == 0) atomicAdd(&cnt[base+dst], 1.f);
}

__global__ void combine_kernel(const float* __restrict__ feat, int fstride, int fcolOff,
                               const float* __restrict__ agg, const float* __restrict__ cnt,
                               float* __restrict__ outp, int ostride, int ocolOff)
{
    int i = blockIdx.x*256 + threadIdx.x;
    if (i >= NTOT*1024) return;
    int n = i >> 10, d = i & 1023;
    float c = fmaxf(cnt[n], 1.f);
    float fv = feat[(size_t)n*fstride + fcolOff + d];
    outp[(size_t)n*ostride + ocolOff + d] = (agg[i]/c) * fv;
}

__global__ void gemm_bias_kernel(const float* __restrict__ A, int lda,
                                 const float* __restrict__ W,
                                 const float* __restrict__ bias,
                                 float* __restrict__ C, int M, int K)
{
    __shared__ float sA[16][17];
    __shared__ float sB[16][64];
    int tx = threadIdx.x & 15, ty = threadIdx.x >> 4;
    int n0 = blockIdx.x*64, m0 = blockIdx.y*16;
    float acc[4] = {0.f,0.f,0.f,0.f};
    for (int k0 = 0; k0 < K; k0 += 16){
        int m = m0 + ty;
        sA[ty][tx] = (m < M) ? A[(size_t)m*lda + k0 + tx] : 0.f;
        #pragma unroll
        for (int j = 0; j < 4; j++)
            sB[ty][tx*4+j] = W[(size_t)(k0+ty)*1024 + n0 + tx*4 + j];
        __syncthreads();
        #pragma unroll
        for (int kk = 0; kk < 16; kk++){
            float a = sA[ty][kk];
            #pragma unroll
            for (int j = 0; j < 4; j++) acc[j] += a * sB[kk][tx*4+j];
        }
        __syncthreads();
    }
    int m = m0 + ty;
    if (m < M){
        #pragma unroll
        for (int j = 0; j < 4; j++)
            C[(size_t)m*1024 + n0 + tx*4 + j] = acc[j] + bias[n0 + tx*4 + j];
    }
}

__global__ void pair_kernel(const float* __restrict__ feat,
                            const float* __restrict__ center,
                            float* __restrict__ bmat)
{
    int s = blockIdx.x, q = blockIdx.y;
    const float* qf = feat + (size_t)(NSUP+q)*1024;
    const float* sf = feat + (size_t)s*1024;
    const float* cf = center + (size_t)(s/5)*1024;
    __shared__ float su[1024];
    __shared__ float rA[256], rB[256], rC[256];
    __shared__ float sS1, sS2;
    int tid = threadIdx.x;

    float S1 = 0.f, S2 = 0.f, M = -1e30f;
    for (int d = tid; d < 1024; d += 256){
        float qd = qf[d], sd = sf[d];
        float df = sd - qd;
        float u = expf(-df*df);
        su[d] = u;
        S2 += u; M = fmaxf(M, u);
        float sc = 0.25f*cf[d] + 0.5f*sd;
        float d2 = sc - qd;
        S1 += expf(-d2*d2);
    }
    rA[tid]=S1; rB[tid]=S2; rC[tid]=M;
    __syncthreads();
    for (int o = 128; o > 0; o >>= 1){
        if (tid < o){ rA[tid]+=rA[tid+o]; rB[tid]+=rB[tid+o]; rC[tid]=fmaxf(rC[tid],rC[tid+o]); }
        __syncthreads();
    }
    if (tid == 0){ sS1 = rA[0]; sS2 = rB[0]; }
    float Mv = rC[0];
    __syncthreads();

    float Se = 0.f;
    for (int d = tid; d < 1024; d += 256) Se += expf(su[d] - Mv);
    rA[tid] = Se;
    __syncthreads();
    for (int o = 128; o > 0; o >>= 1){ if (tid < o) rA[tid]+=rA[tid+o]; __syncthreads(); }
    if (tid == 0)
        bmat[q*NSUP + s] = sS1 + sS2 - 1024.f*(Mv + logf(rA[0]));
}

__global__ void dis_kernel(const float* __restrict__ bmat,
                           const int* __restrict__ sy,
                           float* __restrict__ dis)
{
    int q = blockIdx.x;
    __shared__ float row[NSUP];
    __shared__ float red[128];
    int tid = threadIdx.x;
    float m = -1e30f;
    for (int s = tid; s < NSUP; s += 128){ row[s] = bmat[q*NSUP+s]; m = fmaxf(m, row[s]); }
    red[tid] = m; __syncthreads();
    for (int o = 64; o > 0; o >>= 1){ if (tid < o) red[tid]=fmaxf(red[tid],red[tid+o]); __syncthreads(); }
    float mv = red[0]; __syncthreads();
    float se = 0.f;
    for (int s = tid; s < NSUP; s += 128) se += expf(row[s]-mv);
    red[tid] = se; __syncthreads();
    for (int o = 64; o > 0; o >>= 1){ if (tid < o) red[tid]+=red[tid+o]; __syncthreads(); }
    float lse = mv + logf(red[0]);
    if (tid < NCLS){
        float sum = 0.f, cntc = 0.f;
        for (int s = 0; s < NSUP; s++) if (sy[s]==tid){ sum += row[s]-lse; cntc += 1.f; }
        dis[q*NCLS+tid] = sum / fmaxf(cntc, 1.f);
    }
}

__global__ void center_kernel(const float* __restrict__ feat,
                              const int* __restrict__ sy,
                              const float* __restrict__ center,
                              float* __restrict__ outp)
{
    int c = blockIdx.x;
    int d = blockIdx.y*256 + threadIdx.x;
    __shared__ int ssy[NSUP];
    for (int s = threadIdx.x; s < NSUP; s += 256) ssy[s] = sy[s];
    __syncthreads();
    float sum = 0.f, cnt = 0.f;
    for (int s = 0; s < NSUP; s++) if (ssy[s]==c){ sum += feat[(size_t)s*1024 + d]; cnt += 1.f; }
    outp[c*1024 + d] = (sum/fmaxf(cnt,1.f))*0.5f + 0.25f*center[c*1024 + d];
}

__global__ void loss_kernel(const float* __restrict__ dis,
                            const int* __restrict__ qy,
                            float* __restrict__ outp)
{
    __shared__ float sl[32], sa[32];
    int q = threadIdx.x;
    float l = 0.f, a = 0.f;
    if (q < NQRY){
        const float* r = dis + q*NCLS;
        float best = -1e30f; int arg = 0; float m = -1e30f;
        for (int j = 0; j < NCLS; j++){
            float v = r[j];
            if (v > best){ best = v; arg = j; }
            m = fmaxf(m, v);
        }
        float se = 0.f;
        for (int j = 0; j < NCLS; j++) se += expf(r[j]-m);
        float lse = m + logf(se);
        int y = qy[q];
        l = lse - r[y];
        a = (arg == y) ? 1.f : 0.f;
    }
    sl[threadIdx.x] = l; sa[threadIdx.x] = a;
    __syncthreads();
    if (threadIdx.x == 0){
        float L = 0.f, A = 0.f;
        for (int i = 0; i < 32; i++){ L += sl[i]; A += sa[i]; }
        outp[0] = L; outp[1] = A;
    }
}

// ---------------- host launcher ----------------
extern "C" void kernel_launch(void* const* d_in, const int* in_sizes, int n_in,
                              void* d_out, int out_size)
{
    const float* support_x = (const float*)d_in[0];
    const int*   sup_ei    = (const int*)  d_in[1];
    const int*   sup_y     = (const int*)  d_in[3];
    const float* query_x   = (const float*)d_in[4];
    const int*   qry_ei    = (const int*)  d_in[5];
    const int*   qry_y     = (const int*)  d_in[7];
    const float* center    = (const float*)d_in[8];
    const float* cw1       = (const float*)d_in[9];
    const float* cb1       = (const float*)d_in[10];
    const float* cw_rest   = (const float*)d_in[11];
    const float* cb_rest   = (const float*)d_in[12];
    const float* lin2_w    = (const float*)d_in[13];
    const float* lin2_b    = (const float*)d_in[14];
    const float* mlp_w     = (const float*)d_in[15];
    const float* mlp_b     = (const float*)d_in[16];
    float* out = (float*)d_out;

    int Es = in_sizes[1] / 2;
    int Eq = in_sizes[5] / 2;

    float *padin, *buf0, *buf1, *cat, *tmp, *h2, *feat, *agg, *cnt, *bmat, *dis;
    u64* wdup;
    cudaGetSymbolAddress((void**)&padin, g_padin);
    cudaGetSymbolAddress((void**)&buf0,  g_buf0);
    cudaGetSymbolAddress((void**)&buf1,  g_buf1);
    cudaGetSymbolAddress((void**)&wdup,  g_wdup);
    cudaGetSymbolAddress((void**)&cat,   g_cat);
    cudaGetSymbolAddress((void**)&tmp,   g_tmp);
    cudaGetSymbolAddress((void**)&h2,    g_h2);
    cudaGetSymbolAddress((void**)&feat,  g_feat);
    cudaGetSymbolAddress((void**)&agg,   g_agg);
    cudaGetSymbolAddress((void**)&cnt,   g_cnt);
    cudaGetSymbolAddress((void**)&bmat,  g_b);
    cudaGetSymbolAddress((void**)&dis,   g_dis);

    const int SM_C1 = 2*(3*18*9 + 64*3*9)*8;   // 35424
    const int SM_C2 = 2*(8*18*9 + 64*8*9)*8;   // 94464

    static int attr_done = 0;
    if (!attr_done){
        cudaFuncSetAttribute(convp_kernel<256,3,1>, cudaFuncAttributeMaxDynamicSharedMemorySize, SM_C1);
        cudaFuncSetAttribute(convp_kernel<128,8,8>, cudaFuncAttributeMaxDynamicSharedMemorySize, SM_C2);
        cudaFuncSetAttribute(convp_kernel< 64,8,8>, cudaFuncAttributeMaxDynamicSharedMemorySize, SM_C2);
        cudaFuncSetAttribute(convp_kernel< 32,8,8>, cudaFuncAttributeMaxDynamicSharedMemorySize, SM_C2);
        cudaFuncSetAttribute(convp_kernel< 16,8,8>, cudaFuncAttributeMaxDynamicSharedMemorySize, SM_C2);
        attr_done = 1;
    }

    // ---- prep ----
    {
        size_t total = (size_t)NTOT*3*258*258;
        padin_kernel<<<(unsigned)((total + 255)/256), 256>>>(support_x, query_x, padin);
    }
    wdup_kernel<<<(1728 + 4*36864 + 255)/256, 256>>>(cw1, cw_rest, wdup);
    border_kernel<<<NTOT*64, 64>>>(buf0, 130);
    border_kernel<<<NTOT*64, 64>>>(buf1, 66);

    // ---- CNN ----
    convp_kernel<256,3,1><<<dim3(16*16, NTOT), 512, SM_C1>>>(padin, wdup, cb1, buf0);
    convp_kernel<128,8,8><<<dim3( 8*8, NTOT), 512, SM_C2>>>(buf0, wdup + 1728 + 0*36864, cb_rest + 0,   buf1);
    border_kernel<<<NTOT*64, 64>>>(buf0, 34);
    convp_kernel< 64,8,8><<<dim3( 4*4, NTOT), 512, SM_C2>>>(buf1, wdup + 1728 + 1*36864, cb_rest + 64,  buf0);
    border_kernel<<<NTOT*64, 64>>>(buf1, 18);
    convp_kernel< 32,8,8><<<dim3( 2*2, NTOT), 512, SM_C2>>>(buf0, wdup + 1728 + 2*36864, cb_rest + 128, buf1);
    border_kernel<<<NTOT*64, 64>>>(buf0, 10);
    convp_kernel< 16,8,8><<<dim3(   1, NTOT), 512, SM_C2>>>(buf1, wdup + 1728 + 3*36864, cb_rest + 192, buf0);
    conv6_kernel<<<NTOT, 128>>>(buf0, cw_rest + 4*(64*64*9), cb_rest + 256, cat);

    const int NG = (NTOT*1024 + 255)/256;

    // ---- graph conv 1 ----
    zero_kernel<<<NG,256>>>(agg, NTOT*1024);
    zero_kernel<<<1,256>>>(cnt, NTOT);
    scatter_kernel<<<Es,256>>>(cat, 2048, 0, sup_ei, Es, 0,    agg, cnt);
    scatter_kernel<<<Eq,256>>>(cat, 2048, 0, qry_ei, Eq, NSUP, agg, cnt);
    combine_kernel<<<NG,256>>>(cat, 2048, 0, agg, cnt, tmp, 1024, 0);

    gemm_bias_kernel<<<dim3(16,(NTOT+15)/16),256>>>(tmp, 1024, lin2_w, lin2_b, h2, NTOT, 1024);

    // ---- graph conv 2 ----
    zero_kernel<<<NG,256>>>(agg, NTOT*1024);
    zero_kernel<<<1,256>>>(cnt, NTOT);
    scatter_kernel<<<Es,256>>>(h2, 1024, 0, sup_ei, Es, 0,    agg, cnt);
    scatter_kernel<<<Eq,256>>>(h2, 1024, 0, qry_ei, Eq, NSUP, agg, cnt);
    combine_kernel<<<NG,256>>>(h2, 1024, 0, agg, cnt, cat, 2048, 1024);

    gemm_bias_kernel<<<dim3(16,(NTOT+15)/16),256>>>(cat, 2048, mlp_w, mlp_b, feat, NTOT, 2048);

    pair_kernel<<<dim3(NSUP, NQRY), 256>>>(feat, center, bmat);
    dis_kernel<<<NQRY,128>>>(bmat, sup_y, dis);

    center_kernel<<<dim3(NCLS,4),256>>>(feat, sup_y, center, out + 2);
    loss_kernel<<<1,32>>>(dis, qry_y, out);
}